// round 13
// baseline (speedup 1.0000x reference)
#include <cuda_runtime.h>
#include <cuda_fp16.h>
#include <cstdint>

#define NC_ 4096
#define NP_ 4096
#define DD  1024

#define BM 128
#define BN 128
#define BK 64                                    // fp16 elements per k-tile
#define STAGE_BYTES 32768                        // (128 A + 128 B) rows x 128 B
#define STAGES 3
#define GEMM_SMEM (STAGES * STAGE_BYTES)         // 98304 B

// Scratch.
__device__ __half g_xh[6][(size_t)NC_ * DD];     // fp16 inputs
__device__ __half g_wh[6][(size_t)DD * DD];      // fp16 weights
__device__ __half g_ph[6][(size_t)NC_ * DD];     // fp16 projections (q,k,vT)
__device__ __half g_score[2][(size_t)NC_ * NP_]; // fp16 scores (raw, unscaled)
__device__ __half g_prob[2][(size_t)NC_ * NP_];  // fp16 probabilities

// ---------------------------------------------------------------------------
__device__ __forceinline__ uint32_t smem_u32(const void* p) {
    uint32_t a;
    asm("{ .reg .u64 t; cvta.to.shared.u64 t, %1; cvt.u32.u64 %0, t; }"
        : "=r"(a) : "l"(p));
    return a;
}

__device__ __forceinline__ void cp16u(uint32_t dst, const void* src) {
    asm volatile("cp.async.cg.shared.global [%0], [%1], 16;" :: "r"(dst), "l"(src));
}

__device__ __forceinline__ void ldsm_x4(uint32_t addr, uint32_t* r) {
    asm volatile("ldmatrix.sync.aligned.m8n8.x4.shared.b16 {%0,%1,%2,%3}, [%4];"
                 : "=r"(r[0]), "=r"(r[1]), "=r"(r[2]), "=r"(r[3]) : "r"(addr));
}

__device__ __forceinline__ void mma_f16(float* d, const uint32_t* a, const uint32_t* b) {
    asm volatile(
        "mma.sync.aligned.m16n8k16.row.col.f32.f16.f16.f32 "
        "{%0,%1,%2,%3}, {%4,%5,%6,%7}, {%8,%9}, {%0,%1,%2,%3};"
        : "+f"(d[0]), "+f"(d[1]), "+f"(d[2]), "+f"(d[3])
        : "r"(a[0]), "r"(a[1]), "r"(a[2]), "r"(a[3]), "r"(b[0]), "r"(b[1]));
}

// ---------------------------------------------------------------------------
// Fused fp32 -> fp16 conversion of all 12 tensors in one launch.
// ---------------------------------------------------------------------------
struct Src12 { const float* p[12]; };

__global__ __launch_bounds__(256)
void conv_h12(Src12 srcs, __half* __restrict__ outX, __half* __restrict__ outW) {
    const int nx4 = NC_ * DD / 4;
    const int nw4 = DD * DD / 4;
    const int totX = 6 * nx4;
    const int tot = totX + 6 * nw4;
    for (int i = blockIdx.x * 256 + threadIdx.x; i < tot; i += gridDim.x * 256) {
        const float* src;
        __half2* dst;
        int off;
        if (i < totX) {
            const int seg = i / nx4;
            off = i - seg * nx4;
            src = srcs.p[seg];
            dst = (__half2*)(outX + (size_t)seg * NC_ * DD);
        } else {
            const int j = i - totX;
            const int seg = j / nw4;
            off = j - seg * nw4;
            src = srcs.p[6 + seg];
            dst = (__half2*)(outW + (size_t)seg * DD * DD);
        }
        float4 v = ((const float4*)src)[off];
        dst[2 * off + 0] = __floats2half2_rn(v.x, v.y);
        dst[2 * off + 1] = __floats2half2_rn(v.z, v.w);
    }
}

// ---------------------------------------------------------------------------
// Batched fp16 mma.sync NT GEMM with PER-OP dims: C = A @ B^T (+bias).
//   op.biasMode: 0=none, 1=bias[n], 2=bias[m];  op.outHalf: __half vs float
// 256 threads, 8 warps (2M x 4N), warp tile 64x32, CTA tile 128x128x64.
// SMEM: 128-byte rows, XOR-swizzled; ldmatrix.x4 + fragment ping-pong.
// Producer cp.async for stage kt+2 is spread across the kk loop (2/step).
// CTAs outside op's M/N range exit immediately (shape-merged launches).
// ---------------------------------------------------------------------------
struct GemmOp {
    const __half* A; const __half* B; const float* bias; void* C;
    int M, N, biasMode, outHalf;
};
struct GemmBatch { GemmOp op[4]; };

__global__ __launch_bounds__(256, 2)
void gemm_hb(GemmBatch ops, int K) {
    const GemmOp op = ops.op[blockIdx.z];
    const int bx = blockIdx.x, by = blockIdx.y;
    if (by * BM >= op.M || bx * BN >= op.N) return;

    extern __shared__ __half smh[];
    const uint32_t sbase = smem_u32(smh);
    const int tid = threadIdx.x;
    const int wid = tid >> 5;
    const int lane = tid & 31;
    const int T = K / BK;
    const int N = op.N;

    const __half* gA = op.A + (size_t)(by * BM) * K;
    const __half* gB = op.B + (size_t)(bx * BN) * K;

    // producer addressing: each thread stores 16B at (row, chunk)
    const int srow = tid >> 3;                       // 0..31
    const int schunk = tid & 7;                      // 16B chunk in 128B row
    const uint32_t ssw = (uint32_t)((schunk ^ (srow & 7)) << 4);

    // part p in 0..3: p<2 -> A rows (2 row-groups), p>=2 -> B rows
    auto load_part = [&](int stage, int kt, int p) {
        const uint32_t s = sbase + stage * STAGE_BYTES;
        const int kofs = kt * BK + schunk * 8;
        if (p < 2) {
#pragma unroll
            for (int l = 0; l < 2; l++) {
                const int row = (p * 2 + l) * 32 + srow;
                cp16u(s + row * 128 + ssw, gA + (size_t)row * K + kofs);
            }
        } else {
#pragma unroll
            for (int l = 0; l < 2; l++) {
                const int row = ((p - 2) * 2 + l) * 32 + srow;
                cp16u(s + 16384 + row * 128 + ssw, gB + (size_t)row * K + kofs);
            }
        }
    };

    auto load_tile = [&](int stage, int kt) {
#pragma unroll
        for (int p = 0; p < 4; p++) load_part(stage, kt, p);
        asm volatile("cp.async.commit_group;" ::: "memory");
    };

    load_tile(0, 0);
    load_tile(1, 1);

    const int wm = wid & 1;   // 0..1 (M)
    const int wn = wid >> 1;  // 0..3 (N)
    const int lane7 = lane & 7;

    // ldmatrix per-lane row indices (swizzle XOR reduces to lane7)
    const int aRow = wm * 64 + ((lane >> 3) & 1) * 8 + lane7;   // + mi*16
    const int bRow = wn * 32 + ((lane >> 4) & 1) * 8 + lane7;   // + p*16
    const int aHi = lane >> 4;
    const int bHi = (lane >> 3) & 1;
    uint32_t aCol[4], bCol[4];
#pragma unroll
    for (int kk = 0; kk < 4; kk++) {
        aCol[kk] = (uint32_t)(((2 * kk + aHi) ^ lane7) << 4);
        bCol[kk] = (uint32_t)(((2 * kk + bHi) ^ lane7) << 4);
    }

    float acc[4][4][4] = {};
    uint32_t af[2][4][4], bf[2][2][4];

    for (int kt = 0; kt < T; kt++) {
        if (kt < T - 1)
            asm volatile("cp.async.wait_group 1;" ::: "memory");
        else
            asm volatile("cp.async.wait_group 0;" ::: "memory");
        __syncthreads();

        const bool doLoad = (kt + 2 < T);
        const int lstage = (kt + 2) % STAGES;

        const uint32_t sA = sbase + (kt % STAGES) * STAGE_BYTES;
        const uint32_t sB = sA + 16384;

        // prefetch kk=0 fragments
#pragma unroll
        for (int mi = 0; mi < 4; mi++)
            ldsm_x4(sA + (aRow + mi * 16) * 128 + aCol[0], af[0][mi]);
#pragma unroll
        for (int p = 0; p < 2; p++)
            ldsm_x4(sB + (bRow + p * 16) * 128 + bCol[0], bf[0][p]);

#pragma unroll
        for (int kk = 0; kk < 4; kk++) {   // 4 x k16 per k-tile
            const int cur = kk & 1;
            const int nxt = cur ^ 1;
            // spread producer: one quarter of the stage kt+2 loads per kk
            if (doLoad) load_part(lstage, kt + 2, kk);
            if (kk < 3) {                  // prefetch kk+1 before MMAs of kk
#pragma unroll
                for (int mi = 0; mi < 4; mi++)
                    ldsm_x4(sA + (aRow + mi * 16) * 128 + aCol[kk + 1], af[nxt][mi]);
#pragma unroll
                for (int p = 0; p < 2; p++)
                    ldsm_x4(sB + (bRow + p * 16) * 128 + bCol[kk + 1], bf[nxt][p]);
            }
#pragma unroll
            for (int mi = 0; mi < 4; mi++)
#pragma unroll
                for (int nj = 0; nj < 4; nj++)
                    mma_f16(acc[mi][nj], af[cur][mi], &bf[cur][nj >> 1][(nj & 1) * 2]);
        }
        if (doLoad)
            asm volatile("cp.async.commit_group;" ::: "memory");
    }

    // ---------------- epilogue ----------------
    const int r = lane >> 2;  // 0..7
    const int c = lane & 3;   // 0..3
#pragma unroll
    for (int mi = 0; mi < 4; mi++) {
#pragma unroll
        for (int nj = 0; nj < 4; nj++) {
            const int row0 = by * BM + wm * 64 + mi * 16 + r;
            const int col = bx * BN + wn * 32 + nj * 8 + c * 2;
            float2 v0 = make_float2(acc[mi][nj][0], acc[mi][nj][1]);
            float2 v1 = make_float2(acc[mi][nj][2], acc[mi][nj][3]);
            if (op.biasMode == 1) {
                const float b0 = op.bias[col], b1 = op.bias[col + 1];
                v0.x += b0; v0.y += b1;
                v1.x += b0; v1.y += b1;
            } else if (op.biasMode == 2) {
                const float rb0 = op.bias[row0];
                const float rb1 = op.bias[row0 + 8];
                v0.x += rb0; v0.y += rb0;
                v1.x += rb1; v1.y += rb1;
            }
            if (op.outHalf) {
                __half* C = (__half*)op.C;
                *(__half2*)(C + (size_t)row0 * N + col) = __floats2half2_rn(v0.x, v0.y);
                *(__half2*)(C + (size_t)(row0 + 8) * N + col) = __floats2half2_rn(v1.x, v1.y);
            } else {
                float* C = (float*)op.C;
                *(float2*)(C + (size_t)row0 * N + col) = v0;
                *(float2*)(C + (size_t)(row0 + 8) * N + col) = v1;
            }
        }
    }
}

// ---------------------------------------------------------------------------
// Fused dual softmax over fp16 scores: blocks 0..4095 -> S1, 4096..8191 -> S2.
// fp16 raw scores in, fp16 probs out (scale 1/32 applied here).
// ---------------------------------------------------------------------------
__global__ __launch_bounds__(256)
void softmax_dual(const __half* __restrict__ Sa, __half* __restrict__ Pa,
                  const __half* __restrict__ Sb, __half* __restrict__ Pb) {
    const int blk = blockIdx.x;
    const int row = blk & 4095;
    const __half* p = (blk < 4096 ? Sa : Sb) + (size_t)row * 4096;
    __half* q = (blk < 4096 ? Pa : Pb) + (size_t)row * 4096;
    const int tid = threadIdx.x;
    const float isc = 0.03125f;  // 1/sqrt(1024)

    __shared__ float shm[8];
    __shared__ float shs[8];

    float buf[16];
    float m = -1e30f;
#pragma unroll
    for (int i = 0; i < 2; i++) {        // 2 x uint4 = 16 halves per thread
        uint4 t = ((const uint4*)p)[i * 256 + tid];
        const uint32_t w[4] = {t.x, t.y, t.z, t.w};
#pragma unroll
        for (int j = 0; j < 4; j++) {
            float2 f = __half22float2(*(const __half2*)&w[j]);
            buf[i * 8 + j * 2 + 0] = f.x * isc;
            buf[i * 8 + j * 2 + 1] = f.y * isc;
            m = fmaxf(m, fmaxf(buf[i * 8 + j * 2], buf[i * 8 + j * 2 + 1]));
        }
    }
#pragma unroll
    for (int o = 16; o; o >>= 1) m = fmaxf(m, __shfl_xor_sync(0xffffffffu, m, o));
    if ((tid & 31) == 0) shm[tid >> 5] = m;
    __syncthreads();
    if (tid == 0) {
        float mm = shm[0];
#pragma unroll
        for (int w = 1; w < 8; w++) mm = fmaxf(mm, shm[w]);
        shm[0] = mm;
    }
    __syncthreads();
    m = shm[0];

    float s = 0.f;
#pragma unroll
    for (int i = 0; i < 16; i++) {
        float e = __expf(buf[i] - m);
        buf[i] = e;
        s += e;
    }
#pragma unroll
    for (int o = 16; o; o >>= 1) s += __shfl_xor_sync(0xffffffffu, s, o);
    if ((tid & 31) == 0) shs[tid >> 5] = s;
    __syncthreads();
    if (tid == 0) {
        float ss = shs[0];
#pragma unroll
        for (int w = 1; w < 8; w++) ss += shs[w];
        shs[0] = ss;
    }
    __syncthreads();
    const float r = 1.f / shs[0];

#pragma unroll
    for (int i = 0; i < 2; i++) {
        uint4 t;
        uint32_t* w = (uint32_t*)&t;
#pragma unroll
        for (int j = 0; j < 4; j++) {
            __half2 h = __floats2half2_rn(buf[i * 8 + j * 2] * r,
                                          buf[i * 8 + j * 2 + 1] * r);
            w[j] = *(const uint32_t*)&h;
        }
        ((uint4*)q)[i * 256 + tid] = t;
    }
}

// ---------------------------------------------------------------------------
extern "C" void kernel_launch(void* const* d_in, const int* in_sizes, int n_in,
                              void* d_out, int out_size) {
    const float* X[6];
    for (int i = 0; i < 6; i++) X[i] = (const float*)d_in[i];

    const float *W[6], *Bv[6];
    if (n_in >= 8 && in_sizes[7] == DD) {  // interleaved W,b
        for (int i = 0; i < 6; i++) {
            W[i]  = (const float*)d_in[6 + 2 * i];
            Bv[i] = (const float*)d_in[7 + 2 * i];
        }
    } else {  // grouped
        for (int i = 0; i < 6; i++) {
            W[i]  = (const float*)d_in[6 + i];
            Bv[i] = (const float*)d_in[12 + i];
        }
    }

    __half *xh, *wh, *ph, *score, *prob;
    cudaGetSymbolAddress((void**)&xh, g_xh);
    cudaGetSymbolAddress((void**)&wh, g_wh);
    cudaGetSymbolAddress((void**)&ph, g_ph);
    cudaGetSymbolAddress((void**)&score, g_score);
    cudaGetSymbolAddress((void**)&prob, g_prob);

    __half* XH[6];
    __half* WH[6];
    __half* PH[6];
    for (int i = 0; i < 6; i++) {
        XH[i] = xh + (size_t)i * NC_ * DD;
        WH[i] = wh + (size_t)i * DD * DD;
        PH[i] = ph + (size_t)i * NC_ * DD;
    }
    __half* S1 = score;                      // [NC, NP] fp16
    __half* S2 = score + (size_t)NC_ * NP_;  // [NP, NC] fp16
    __half* P1 = prob;
    __half* P2 = prob + (size_t)NC_ * NP_;

    // fp32 -> fp16 conversion of all inputs & weights, one launch
    {
        Src12 s;
        for (int i = 0; i < 6; i++) { s.p[i] = X[i]; s.p[6 + i] = W[i]; }
        conv_h12<<<2960, 256>>>(s, xh, wh);
    }

    cudaFuncSetAttribute(gemm_hb, cudaFuncAttributeMaxDynamicSharedMemorySize, GEMM_SMEM);
    dim3 blk(256);

    // 4 q/k projections -> fp16, one launch (bias per column)
    {
        GemmBatch b;
        b.op[0] = {XH[0], WH[0], Bv[0], PH[0], NC_, DD, 1, 1};
        b.op[1] = {XH[1], WH[1], Bv[1], PH[1], NC_, DD, 1, 1};
        b.op[2] = {XH[3], WH[3], Bv[3], PH[3], NP_, DD, 1, 1};
        b.op[3] = {XH[4], WH[4], Bv[4], PH[4], NP_, DD, 1, 1};
        dim3 g(DD / BN, NC_ / BM, 4);
        gemm_hb<<<g, blk, GEMM_SMEM>>>(b, DD);
    }
    // 2 score GEMMs (fp16 out) + 2 transposed v projections, ONE merged launch.
    {
        GemmBatch b;
        b.op[0] = {PH[0], PH[4], nullptr, S1, NC_, NP_, 0, 1};
        b.op[1] = {PH[3], PH[1], nullptr, S2, NP_, NC_, 0, 1};
        b.op[2] = {WH[2], XH[2], Bv[2], PH[2], DD, NC_, 2, 1};
        b.op[3] = {WH[5], XH[5], Bv[5], PH[5], DD, NP_, 2, 1};
        dim3 g(NP_ / BN, NC_ / BM, 4);   // v-proj slices exit early
        gemm_hb<<<g, blk, GEMM_SMEM>>>(b, DD);
    }

    softmax_dual<<<2 * NC_, 256>>>(S1, P1, S2, P2);

    float* out = (float*)d_out;
    // 2 PV GEMMs -> fp32 outputs, one launch
    {
        GemmBatch b;
        b.op[0] = {P1, PH[5], nullptr, out, NC_, DD, 0, 0};
        b.op[1] = {P2, PH[2], nullptr, out + (size_t)NC_ * DD, NP_, DD, 0, 0};
        b.op[2] = b.op[0]; b.op[3] = b.op[0];
        dim3 g(DD / BN, NC_ / BM, 2);
        gemm_hb<<<g, blk, GEMM_SMEM>>>(b, NP_);
    }
}

// round 14
// speedup vs baseline: 1.0185x; 1.0185x over previous
#include <cuda_runtime.h>
#include <cuda_fp16.h>
#include <cstdint>

#define NC_ 4096
#define NP_ 4096
#define DD  1024

#define BM 128
#define BN 128
#define BK 64                                    // fp16 elements per k-tile
#define STAGE_BYTES 32768                        // (128 A + 128 B) rows x 128 B
#define STAGES 3
#define GEMM_SMEM (STAGES * STAGE_BYTES)         // 98304 B

// Scratch.
__device__ __half g_xh[6][(size_t)NC_ * DD];     // fp16 inputs
__device__ __half g_wh[6][(size_t)DD * DD];      // fp16 weights
__device__ __half g_ph[6][(size_t)NC_ * DD];     // fp16 projections (q,k,vT)
__device__ __half g_score[2][(size_t)NC_ * NP_]; // fp16 scores (raw, unscaled)
__device__ __half g_prob[2][(size_t)NC_ * NP_];  // fp16 probabilities

// ---------------------------------------------------------------------------
__device__ __forceinline__ uint32_t smem_u32(const void* p) {
    uint32_t a;
    asm("{ .reg .u64 t; cvta.to.shared.u64 t, %1; cvt.u32.u64 %0, t; }"
        : "=r"(a) : "l"(p));
    return a;
}

__device__ __forceinline__ void cp16u(uint32_t dst, const void* src) {
    asm volatile("cp.async.cg.shared.global [%0], [%1], 16;" :: "r"(dst), "l"(src));
}

__device__ __forceinline__ void ldsm_x4(uint32_t addr, uint32_t* r) {
    asm volatile("ldmatrix.sync.aligned.m8n8.x4.shared.b16 {%0,%1,%2,%3}, [%4];"
                 : "=r"(r[0]), "=r"(r[1]), "=r"(r[2]), "=r"(r[3]) : "r"(addr));
}

__device__ __forceinline__ void mma_f16(float* d, const uint32_t* a, const uint32_t* b) {
    asm volatile(
        "mma.sync.aligned.m16n8k16.row.col.f32.f16.f16.f32 "
        "{%0,%1,%2,%3}, {%4,%5,%6,%7}, {%8,%9}, {%0,%1,%2,%3};"
        : "+f"(d[0]), "+f"(d[1]), "+f"(d[2]), "+f"(d[3])
        : "r"(a[0]), "r"(a[1]), "r"(a[2]), "r"(a[3]), "r"(b[0]), "r"(b[1]));
}

// ---------------------------------------------------------------------------
// Fused fp32 -> fp16 conversion of all 12 tensors in one launch.
// ---------------------------------------------------------------------------
struct Src12 { const float* p[12]; };

__global__ __launch_bounds__(256)
void conv_h12(Src12 srcs, __half* __restrict__ outX, __half* __restrict__ outW) {
    const int nx4 = NC_ * DD / 4;
    const int nw4 = DD * DD / 4;
    const int totX = 6 * nx4;
    const int tot = totX + 6 * nw4;
    for (int i = blockIdx.x * 256 + threadIdx.x; i < tot; i += gridDim.x * 256) {
        const float* src;
        __half2* dst;
        int off;
        if (i < totX) {
            const int seg = i / nx4;
            off = i - seg * nx4;
            src = srcs.p[seg];
            dst = (__half2*)(outX + (size_t)seg * NC_ * DD);
        } else {
            const int j = i - totX;
            const int seg = j / nw4;
            off = j - seg * nw4;
            src = srcs.p[6 + seg];
            dst = (__half2*)(outW + (size_t)seg * DD * DD);
        }
        float4 v = ((const float4*)src)[off];
        dst[2 * off + 0] = __floats2half2_rn(v.x, v.y);
        dst[2 * off + 1] = __floats2half2_rn(v.z, v.w);
    }
}

// ---------------------------------------------------------------------------
// Batched fp16 mma.sync NT GEMM with PER-OP dims: C = A @ B^T (+bias).
//   op.biasMode: 0=none, 1=bias[n], 2=bias[m];  op.outHalf: __half vs float
// 256 threads, 8 warps (2M x 4N), warp tile 64x32, CTA tile 128x128x64.
// SMEM: 128-byte rows, XOR-swizzled; ldmatrix.x4 + fragment ping-pong.
// Per k-tile: kk=0 LDSM prefetch issues BEFORE the producer cp.async burst.
// CTAs outside op's M/N range exit immediately (shape-merged launches).
// ---------------------------------------------------------------------------
struct GemmOp {
    const __half* A; const __half* B; const float* bias; void* C;
    int M, N, biasMode, outHalf;
};
struct GemmBatch { GemmOp op[4]; };

__global__ __launch_bounds__(256, 2)
void gemm_hb(GemmBatch ops, int K) {
    const GemmOp op = ops.op[blockIdx.z];
    const int bx = blockIdx.x, by = blockIdx.y;
    if (by * BM >= op.M || bx * BN >= op.N) return;

    extern __shared__ __half smh[];
    const uint32_t sbase = smem_u32(smh);
    const int tid = threadIdx.x;
    const int wid = tid >> 5;
    const int lane = tid & 31;
    const int T = K / BK;
    const int N = op.N;

    const __half* gA = op.A + (size_t)(by * BM) * K;
    const __half* gB = op.B + (size_t)(bx * BN) * K;

    // producer addressing: each thread stores 16B at (row, chunk)
    const int srow = tid >> 3;                       // 0..31
    const int schunk = tid & 7;                      // 16B chunk in 128B row
    const uint32_t ssw = (uint32_t)((schunk ^ (srow & 7)) << 4);

    auto load_tile = [&](int stage, int kt) {
        const uint32_t s = sbase + stage * STAGE_BYTES;
        const int kofs = kt * BK + schunk * 8;
#pragma unroll
        for (int l = 0; l < 4; l++) {  // A rows
            const int row = l * 32 + srow;
            cp16u(s + row * 128 + ssw, gA + (size_t)row * K + kofs);
        }
#pragma unroll
        for (int l = 0; l < 4; l++) {  // B rows
            const int row = l * 32 + srow;
            cp16u(s + 16384 + row * 128 + ssw, gB + (size_t)row * K + kofs);
        }
        asm volatile("cp.async.commit_group;" ::: "memory");
    };

    load_tile(0, 0);
    load_tile(1, 1);

    const int wm = wid & 1;   // 0..1 (M)
    const int wn = wid >> 1;  // 0..3 (N)
    const int lane7 = lane & 7;

    // ldmatrix per-lane row indices (swizzle XOR reduces to lane7)
    const int aRow = wm * 64 + ((lane >> 3) & 1) * 8 + lane7;   // + mi*16
    const int bRow = wn * 32 + ((lane >> 4) & 1) * 8 + lane7;   // + p*16
    const int aHi = lane >> 4;
    const int bHi = (lane >> 3) & 1;
    uint32_t aCol[4], bCol[4];
#pragma unroll
    for (int kk = 0; kk < 4; kk++) {
        aCol[kk] = (uint32_t)(((2 * kk + aHi) ^ lane7) << 4);
        bCol[kk] = (uint32_t)(((2 * kk + bHi) ^ lane7) << 4);
    }

    float acc[4][4][4] = {};
    uint32_t af[2][4][4], bf[2][2][4];

    for (int kt = 0; kt < T; kt++) {
        if (kt < T - 1)
            asm volatile("cp.async.wait_group 1;" ::: "memory");
        else
            asm volatile("cp.async.wait_group 0;" ::: "memory");
        __syncthreads();

        const uint32_t sA = sbase + (kt % STAGES) * STAGE_BYTES;
        const uint32_t sB = sA + 16384;

        // CRITICAL-PATH FIRST: prefetch kk=0 fragments before producer burst
#pragma unroll
        for (int mi = 0; mi < 4; mi++)
            ldsm_x4(sA + (aRow + mi * 16) * 128 + aCol[0], af[0][mi]);
#pragma unroll
        for (int p = 0; p < 2; p++)
            ldsm_x4(sB + (bRow + p * 16) * 128 + bCol[0], bf[0][p]);

        // producer burst for stage kt+2 (fills LSU under the MMA shadow)
        if (kt + 2 < T) load_tile((kt + 2) % STAGES, kt + 2);

#pragma unroll
        for (int kk = 0; kk < 4; kk++) {   // 4 x k16 per k-tile
            const int cur = kk & 1;
            const int nxt = cur ^ 1;
            if (kk < 3) {                  // prefetch kk+1 before MMAs of kk
#pragma unroll
                for (int mi = 0; mi < 4; mi++)
                    ldsm_x4(sA + (aRow + mi * 16) * 128 + aCol[kk + 1], af[nxt][mi]);
#pragma unroll
                for (int p = 0; p < 2; p++)
                    ldsm_x4(sB + (bRow + p * 16) * 128 + bCol[kk + 1], bf[nxt][p]);
            }
#pragma unroll
            for (int mi = 0; mi < 4; mi++)
#pragma unroll
                for (int nj = 0; nj < 4; nj++)
                    mma_f16(acc[mi][nj], af[cur][mi], &bf[cur][nj >> 1][(nj & 1) * 2]);
        }
    }

    // ---------------- epilogue ----------------
    const int r = lane >> 2;  // 0..7
    const int c = lane & 3;   // 0..3
#pragma unroll
    for (int mi = 0; mi < 4; mi++) {
#pragma unroll
        for (int nj = 0; nj < 4; nj++) {
            const int row0 = by * BM + wm * 64 + mi * 16 + r;
            const int col = bx * BN + wn * 32 + nj * 8 + c * 2;
            float2 v0 = make_float2(acc[mi][nj][0], acc[mi][nj][1]);
            float2 v1 = make_float2(acc[mi][nj][2], acc[mi][nj][3]);
            if (op.biasMode == 1) {
                const float b0 = op.bias[col], b1 = op.bias[col + 1];
                v0.x += b0; v0.y += b1;
                v1.x += b0; v1.y += b1;
            } else if (op.biasMode == 2) {
                const float rb0 = op.bias[row0];
                const float rb1 = op.bias[row0 + 8];
                v0.x += rb0; v0.y += rb0;
                v1.x += rb1; v1.y += rb1;
            }
            if (op.outHalf) {
                __half* C = (__half*)op.C;
                *(__half2*)(C + (size_t)row0 * N + col) = __floats2half2_rn(v0.x, v0.y);
                *(__half2*)(C + (size_t)(row0 + 8) * N + col) = __floats2half2_rn(v1.x, v1.y);
            } else {
                float* C = (float*)op.C;
                *(float2*)(C + (size_t)row0 * N + col) = v0;
                *(float2*)(C + (size_t)(row0 + 8) * N + col) = v1;
            }
        }
    }
}

// ---------------------------------------------------------------------------
// Fused dual softmax over fp16 scores: blocks 0..4095 -> S1, 4096..8191 -> S2.
// fp16 raw scores in, fp16 probs out (scale 1/32 applied here).
// ---------------------------------------------------------------------------
__global__ __launch_bounds__(256)
void softmax_dual(const __half* __restrict__ Sa, __half* __restrict__ Pa,
                  const __half* __restrict__ Sb, __half* __restrict__ Pb) {
    const int blk = blockIdx.x;
    const int row = blk & 4095;
    const __half* p = (blk < 4096 ? Sa : Sb) + (size_t)row * 4096;
    __half* q = (blk < 4096 ? Pa : Pb) + (size_t)row * 4096;
    const int tid = threadIdx.x;
    const float isc = 0.03125f;  // 1/sqrt(1024)

    __shared__ float shm[8];
    __shared__ float shs[8];

    float buf[16];
    float m = -1e30f;
#pragma unroll
    for (int i = 0; i < 2; i++) {        // 2 x uint4 = 16 halves per thread
        uint4 t = ((const uint4*)p)[i * 256 + tid];
        const uint32_t w[4] = {t.x, t.y, t.z, t.w};
#pragma unroll
        for (int j = 0; j < 4; j++) {
            float2 f = __half22float2(*(const __half2*)&w[j]);
            buf[i * 8 + j * 2 + 0] = f.x * isc;
            buf[i * 8 + j * 2 + 1] = f.y * isc;
            m = fmaxf(m, fmaxf(buf[i * 8 + j * 2], buf[i * 8 + j * 2 + 1]));
        }
    }
#pragma unroll
    for (int o = 16; o; o >>= 1) m = fmaxf(m, __shfl_xor_sync(0xffffffffu, m, o));
    if ((tid & 31) == 0) shm[tid >> 5] = m;
    __syncthreads();
    if (tid == 0) {
        float mm = shm[0];
#pragma unroll
        for (int w = 1; w < 8; w++) mm = fmaxf(mm, shm[w]);
        shm[0] = mm;
    }
    __syncthreads();
    m = shm[0];

    float s = 0.f;
#pragma unroll
    for (int i = 0; i < 16; i++) {
        float e = __expf(buf[i] - m);
        buf[i] = e;
        s += e;
    }
#pragma unroll
    for (int o = 16; o; o >>= 1) s += __shfl_xor_sync(0xffffffffu, s, o);
    if ((tid & 31) == 0) shs[tid >> 5] = s;
    __syncthreads();
    if (tid == 0) {
        float ss = shs[0];
#pragma unroll
        for (int w = 1; w < 8; w++) ss += shs[w];
        shs[0] = ss;
    }
    __syncthreads();
    const float r = 1.f / shs[0];

#pragma unroll
    for (int i = 0; i < 2; i++) {
        uint4 t;
        uint32_t* w = (uint32_t*)&t;
#pragma unroll
        for (int j = 0; j < 4; j++) {
            __half2 h = __floats2half2_rn(buf[i * 8 + j * 2] * r,
                                          buf[i * 8 + j * 2 + 1] * r);
            w[j] = *(const uint32_t*)&h;
        }
        ((uint4*)q)[i * 256 + tid] = t;
    }
}

// ---------------------------------------------------------------------------
extern "C" void kernel_launch(void* const* d_in, const int* in_sizes, int n_in,
                              void* d_out, int out_size) {
    const float* X[6];
    for (int i = 0; i < 6; i++) X[i] = (const float*)d_in[i];

    const float *W[6], *Bv[6];
    if (n_in >= 8 && in_sizes[7] == DD) {  // interleaved W,b
        for (int i = 0; i < 6; i++) {
            W[i]  = (const float*)d_in[6 + 2 * i];
            Bv[i] = (const float*)d_in[7 + 2 * i];
        }
    } else {  // grouped
        for (int i = 0; i < 6; i++) {
            W[i]  = (const float*)d_in[6 + i];
            Bv[i] = (const float*)d_in[12 + i];
        }
    }

    __half *xh, *wh, *ph, *score, *prob;
    cudaGetSymbolAddress((void**)&xh, g_xh);
    cudaGetSymbolAddress((void**)&wh, g_wh);
    cudaGetSymbolAddress((void**)&ph, g_ph);
    cudaGetSymbolAddress((void**)&score, g_score);
    cudaGetSymbolAddress((void**)&prob, g_prob);

    __half* XH[6];
    __half* WH[6];
    __half* PH[6];
    for (int i = 0; i < 6; i++) {
        XH[i] = xh + (size_t)i * NC_ * DD;
        WH[i] = wh + (size_t)i * DD * DD;
        PH[i] = ph + (size_t)i * NC_ * DD;
    }
    __half* S1 = score;                      // [NC, NP] fp16
    __half* S2 = score + (size_t)NC_ * NP_;  // [NP, NC] fp16
    __half* P1 = prob;
    __half* P2 = prob + (size_t)NC_ * NP_;

    // fp32 -> fp16 conversion of all inputs & weights, one launch
    {
        Src12 s;
        for (int i = 0; i < 6; i++) { s.p[i] = X[i]; s.p[6 + i] = W[i]; }
        conv_h12<<<2400, 256>>>(s, xh, wh);
    }

    cudaFuncSetAttribute(gemm_hb, cudaFuncAttributeMaxDynamicSharedMemorySize, GEMM_SMEM);
    dim3 blk(256);

    // 4 q/k projections -> fp16, one launch (bias per column)
    {
        GemmBatch b;
        b.op[0] = {XH[0], WH[0], Bv[0], PH[0], NC_, DD, 1, 1};
        b.op[1] = {XH[1], WH[1], Bv[1], PH[1], NC_, DD, 1, 1};
        b.op[2] = {XH[3], WH[3], Bv[3], PH[3], NP_, DD, 1, 1};
        b.op[3] = {XH[4], WH[4], Bv[4], PH[4], NP_, DD, 1, 1};
        dim3 g(DD / BN, NC_ / BM, 4);
        gemm_hb<<<g, blk, GEMM_SMEM>>>(b, DD);
    }
    // 2 score GEMMs (fp16 out) + 2 transposed v projections, ONE merged launch.
    {
        GemmBatch b;
        b.op[0] = {PH[0], PH[4], nullptr, S1, NC_, NP_, 0, 1};
        b.op[1] = {PH[3], PH[1], nullptr, S2, NP_, NC_, 0, 1};
        b.op[2] = {WH[2], XH[2], Bv[2], PH[2], DD, NC_, 2, 1};
        b.op[3] = {WH[5], XH[5], Bv[5], PH[5], DD, NP_, 2, 1};
        dim3 g(NP_ / BN, NC_ / BM, 4);   // v-proj slices exit early
        gemm_hb<<<g, blk, GEMM_SMEM>>>(b, DD);
    }

    softmax_dual<<<2 * NC_, 256>>>(S1, P1, S2, P2);

    float* out = (float*)d_out;
    // 2 PV GEMMs -> fp32 outputs, one launch
    {
        GemmBatch b;
        b.op[0] = {P1, PH[5], nullptr, out, NC_, DD, 0, 0};
        b.op[1] = {P2, PH[2], nullptr, out + (size_t)NC_ * DD, NP_, DD, 0, 0};
        b.op[2] = b.op[0]; b.op[3] = b.op[0];
        dim3 g(DD / BN, NC_ / BM, 2);
        gemm_hb<<<g, blk, GEMM_SMEM>>>(b, NP_);
    }
}

// round 15
// speedup vs baseline: 1.0574x; 1.0383x over previous
#include <cuda_runtime.h>
#include <cuda_fp16.h>
#include <cstdint>

#define NC_ 4096
#define NP_ 4096
#define DD  1024

#define BM 128
#define BN 128
#define BK 64                                    // fp16 elements per k-tile
#define STAGE_BYTES 32768                        // (128 A + 128 B) rows x 128 B
#define STAGES 3
#define GEMM_SMEM (STAGES * STAGE_BYTES)         // 98304 B

// Scratch.
__device__ __half g_xh[6][(size_t)NC_ * DD];     // fp16 inputs
__device__ __half g_wh[6][(size_t)DD * DD];      // fp16 weights
__device__ __half g_ph[6][(size_t)NC_ * DD];     // fp16 projections (q,k,vT)
__device__ __half g_E[2][(size_t)NC_ * NP_];     // fp16 unnormalized exp(scores)
__device__ float  g_rsp[2][32][4096];            // per-column-block rowsum partials
__device__ float  g_rowsum[2][4096];             // final row sums

// ---------------------------------------------------------------------------
__device__ __forceinline__ uint32_t smem_u32(const void* p) {
    uint32_t a;
    asm("{ .reg .u64 t; cvta.to.shared.u64 t, %1; cvt.u32.u64 %0, t; }"
        : "=r"(a) : "l"(p));
    return a;
}

__device__ __forceinline__ void cp16u(uint32_t dst, const void* src) {
    asm volatile("cp.async.cg.shared.global [%0], [%1], 16;" :: "r"(dst), "l"(src));
}

__device__ __forceinline__ void ldsm_x4(uint32_t addr, uint32_t* r) {
    asm volatile("ldmatrix.sync.aligned.m8n8.x4.shared.b16 {%0,%1,%2,%3}, [%4];"
                 : "=r"(r[0]), "=r"(r[1]), "=r"(r[2]), "=r"(r[3]) : "r"(addr));
}

__device__ __forceinline__ void mma_f16(float* d, const uint32_t* a, const uint32_t* b) {
    asm volatile(
        "mma.sync.aligned.m16n8k16.row.col.f32.f16.f16.f32 "
        "{%0,%1,%2,%3}, {%4,%5,%6,%7}, {%8,%9}, {%0,%1,%2,%3};"
        : "+f"(d[0]), "+f"(d[1]), "+f"(d[2]), "+f"(d[3])
        : "r"(a[0]), "r"(a[1]), "r"(a[2]), "r"(a[3]), "r"(b[0]), "r"(b[1]));
}

// ---------------------------------------------------------------------------
// Fused fp32 -> fp16 conversion of all 12 tensors in one launch.
// ---------------------------------------------------------------------------
struct Src12 { const float* p[12]; };

__global__ __launch_bounds__(256)
void conv_h12(Src12 srcs, __half* __restrict__ outX, __half* __restrict__ outW) {
    const int nx4 = NC_ * DD / 4;
    const int nw4 = DD * DD / 4;
    const int totX = 6 * nx4;
    const int tot = totX + 6 * nw4;
    for (int i = blockIdx.x * 256 + threadIdx.x; i < tot; i += gridDim.x * 256) {
        const float* src;
        __half2* dst;
        int off;
        if (i < totX) {
            const int seg = i / nx4;
            off = i - seg * nx4;
            src = srcs.p[seg];
            dst = (__half2*)(outX + (size_t)seg * NC_ * DD);
        } else {
            const int j = i - totX;
            const int seg = j / nw4;
            off = j - seg * nw4;
            src = srcs.p[6 + seg];
            dst = (__half2*)(outW + (size_t)seg * DD * DD);
        }
        float4 v = ((const float4*)src)[off];
        dst[2 * off + 0] = __floats2half2_rn(v.x, v.y);
        dst[2 * off + 1] = __floats2half2_rn(v.z, v.w);
    }
}

// ---------------------------------------------------------------------------
// Row-sum reduction: g_rsp[s][32][4096] -> g_rowsum[s][4096].
// ---------------------------------------------------------------------------
__global__ __launch_bounds__(256)
void rowsum_reduce(const float* __restrict__ rsp, float* __restrict__ rs) {
    const int i = blockIdx.x * 256 + threadIdx.x;   // 0..8191
    if (i < 2 * 4096) {
        const int s = i >> 12, row = i & 4095;
        const float* p = rsp + (size_t)s * 32 * 4096 + row;
        float t = 0.f;
#pragma unroll
        for (int b = 0; b < 32; b++) t += p[b * 4096];
        rs[s * 4096 + row] = t;
    }
}

// ---------------------------------------------------------------------------
// Batched fp16 mma.sync NT GEMM with PER-OP dims: C = A @ B^T (+epilogue).
//   op.biasMode: 0=none, 1=bias[n], 2=bias[m],
//                3=exp(x/32) + rowsum partials (fp16 out, rsum=[32][4096]),
//                4=scale rows by 1/rsum[row]   (fp32 out, rsum=[4096])
// 256 threads, 8 warps (2M x 4N), warp tile 64x32, CTA tile 128x128x64.
// SMEM: 128-byte rows, XOR-swizzled; ldmatrix.x4 + fragment ping-pong.
// CTAs outside op's M/N range exit immediately (shape-merged launches).
// ---------------------------------------------------------------------------
struct GemmOp {
    const __half* A; const __half* B; const float* bias; void* C;
    float* rsum;
    int M, N, biasMode, outHalf;
};
struct GemmBatch { GemmOp op[4]; };

__global__ __launch_bounds__(256, 2)
void gemm_hb(GemmBatch ops, int K) {
    const GemmOp op = ops.op[blockIdx.z];
    const int bx = blockIdx.x, by = blockIdx.y;
    if (by * BM >= op.M || bx * BN >= op.N) return;

    extern __shared__ __half smh[];
    const uint32_t sbase = smem_u32(smh);
    const int tid = threadIdx.x;
    const int wid = tid >> 5;
    const int lane = tid & 31;
    const int T = K / BK;
    const int N = op.N;

    const __half* gA = op.A + (size_t)(by * BM) * K;
    const __half* gB = op.B + (size_t)(bx * BN) * K;

    // producer addressing: each thread stores 16B at (row, chunk)
    const int srow = tid >> 3;                       // 0..31
    const int schunk = tid & 7;                      // 16B chunk in 128B row
    const uint32_t ssw = (uint32_t)((schunk ^ (srow & 7)) << 4);

    auto load_tile = [&](int stage, int kt) {
        const uint32_t s = sbase + stage * STAGE_BYTES;
        const int kofs = kt * BK + schunk * 8;
#pragma unroll
        for (int l = 0; l < 4; l++) {  // A rows
            const int row = l * 32 + srow;
            cp16u(s + row * 128 + ssw, gA + (size_t)row * K + kofs);
        }
#pragma unroll
        for (int l = 0; l < 4; l++) {  // B rows
            const int row = l * 32 + srow;
            cp16u(s + 16384 + row * 128 + ssw, gB + (size_t)row * K + kofs);
        }
        asm volatile("cp.async.commit_group;" ::: "memory");
    };

    load_tile(0, 0);
    load_tile(1, 1);

    const int wm = wid & 1;   // 0..1 (M)
    const int wn = wid >> 1;  // 0..3 (N)
    const int lane7 = lane & 7;

    // ldmatrix per-lane row indices (swizzle XOR reduces to lane7)
    const int aRow = wm * 64 + ((lane >> 3) & 1) * 8 + lane7;   // + mi*16
    const int bRow = wn * 32 + ((lane >> 4) & 1) * 8 + lane7;   // + p*16
    const int aHi = lane >> 4;
    const int bHi = (lane >> 3) & 1;
    uint32_t aCol[4], bCol[4];
#pragma unroll
    for (int kk = 0; kk < 4; kk++) {
        aCol[kk] = (uint32_t)(((2 * kk + aHi) ^ lane7) << 4);
        bCol[kk] = (uint32_t)(((2 * kk + bHi) ^ lane7) << 4);
    }

    float acc[4][4][4] = {};
    uint32_t af[2][4][4], bf[2][2][4];

    for (int kt = 0; kt < T; kt++) {
        if (kt < T - 1)
            asm volatile("cp.async.wait_group 1;" ::: "memory");
        else
            asm volatile("cp.async.wait_group 0;" ::: "memory");
        __syncthreads();

        if (kt + 2 < T) load_tile((kt + 2) % STAGES, kt + 2);

        const uint32_t sA = sbase + (kt % STAGES) * STAGE_BYTES;
        const uint32_t sB = sA + 16384;

        // prefetch kk=0 fragments
#pragma unroll
        for (int mi = 0; mi < 4; mi++)
            ldsm_x4(sA + (aRow + mi * 16) * 128 + aCol[0], af[0][mi]);
#pragma unroll
        for (int p = 0; p < 2; p++)
            ldsm_x4(sB + (bRow + p * 16) * 128 + bCol[0], bf[0][p]);

#pragma unroll
        for (int kk = 0; kk < 4; kk++) {   // 4 x k16 per k-tile
            const int cur = kk & 1;
            const int nxt = cur ^ 1;
            if (kk < 3) {                  // prefetch kk+1 before MMAs of kk
#pragma unroll
                for (int mi = 0; mi < 4; mi++)
                    ldsm_x4(sA + (aRow + mi * 16) * 128 + aCol[kk + 1], af[nxt][mi]);
#pragma unroll
                for (int p = 0; p < 2; p++)
                    ldsm_x4(sB + (bRow + p * 16) * 128 + bCol[kk + 1], bf[nxt][p]);
            }
#pragma unroll
            for (int mi = 0; mi < 4; mi++)
#pragma unroll
                for (int nj = 0; nj < 4; nj++)
                    mma_f16(acc[mi][nj], af[cur][mi], &bf[cur][nj >> 1][(nj & 1) * 2]);
        }
    }

    // ---------------- epilogue ----------------
    const int r = lane >> 2;  // 0..7
    const int c = lane & 3;   // 0..3

    if (op.biasMode == 3) {
        // exp(x/32) -> fp16 E, plus deterministic per-CTA row-sum partials
        const float isc = 0.03125f;
        float rs0[4], rs1[4];
#pragma unroll
        for (int mi = 0; mi < 4; mi++) { rs0[mi] = 0.f; rs1[mi] = 0.f; }
        __half* C = (__half*)op.C;
#pragma unroll
        for (int mi = 0; mi < 4; mi++) {
            const int row0 = by * BM + wm * 64 + mi * 16 + r;
#pragma unroll
            for (int nj = 0; nj < 4; nj++) {
                const int col = bx * BN + wn * 32 + nj * 8 + c * 2;
                const float e00 = __expf(acc[mi][nj][0] * isc);
                const float e01 = __expf(acc[mi][nj][1] * isc);
                const float e10 = __expf(acc[mi][nj][2] * isc);
                const float e11 = __expf(acc[mi][nj][3] * isc);
                rs0[mi] += e00 + e01;
                rs1[mi] += e10 + e11;
                *(__half2*)(C + (size_t)row0 * N + col) = __floats2half2_rn(e00, e01);
                *(__half2*)(C + (size_t)(row0 + 8) * N + col) = __floats2half2_rn(e10, e11);
            }
        }
        // reduce over c lanes (lane bits 0-1)
#pragma unroll
        for (int mi = 0; mi < 4; mi++) {
            rs0[mi] += __shfl_xor_sync(0xffffffffu, rs0[mi], 1);
            rs0[mi] += __shfl_xor_sync(0xffffffffu, rs0[mi], 2);
            rs1[mi] += __shfl_xor_sync(0xffffffffu, rs1[mi], 1);
            rs1[mi] += __shfl_xor_sync(0xffffffffu, rs1[mi], 2);
        }
        __syncthreads();                       // safe SMEM reuse
        float* sr = (float*)smh;               // [4][128]
        if (c == 0) {
#pragma unroll
            for (int mi = 0; mi < 4; mi++) {
                sr[wn * 128 + wm * 64 + mi * 16 + r] = rs0[mi];
                sr[wn * 128 + wm * 64 + mi * 16 + r + 8] = rs1[mi];
            }
        }
        __syncthreads();
        if (tid < 128) {
            const float t = sr[tid] + sr[128 + tid] + sr[256 + tid] + sr[384 + tid];
            op.rsum[(size_t)bx * 4096 + by * BM + tid] = t;
        }
        return;
    }

#pragma unroll
    for (int mi = 0; mi < 4; mi++) {
        const int row0 = by * BM + wm * 64 + mi * 16 + r;
        float inv0 = 1.f, inv1 = 1.f;
        if (op.biasMode == 4) {
            inv0 = 1.f / op.rsum[row0];
            inv1 = 1.f / op.rsum[row0 + 8];
        }
#pragma unroll
        for (int nj = 0; nj < 4; nj++) {
            const int col = bx * BN + wn * 32 + nj * 8 + c * 2;
            float2 v0 = make_float2(acc[mi][nj][0], acc[mi][nj][1]);
            float2 v1 = make_float2(acc[mi][nj][2], acc[mi][nj][3]);
            if (op.biasMode == 1) {
                const float b0 = op.bias[col], b1 = op.bias[col + 1];
                v0.x += b0; v0.y += b1;
                v1.x += b0; v1.y += b1;
            } else if (op.biasMode == 2) {
                const float rb0 = op.bias[row0];
                const float rb1 = op.bias[row0 + 8];
                v0.x += rb0; v0.y += rb0;
                v1.x += rb1; v1.y += rb1;
            } else if (op.biasMode == 4) {
                v0.x *= inv0; v0.y *= inv0;
                v1.x *= inv1; v1.y *= inv1;
            }
            if (op.outHalf) {
                __half* C = (__half*)op.C;
                *(__half2*)(C + (size_t)row0 * N + col) = __floats2half2_rn(v0.x, v0.y);
                *(__half2*)(C + (size_t)(row0 + 8) * N + col) = __floats2half2_rn(v1.x, v1.y);
            } else {
                float* C = (float*)op.C;
                *(float2*)(C + (size_t)row0 * N + col) = v0;
                *(float2*)(C + (size_t)(row0 + 8) * N + col) = v1;
            }
        }
    }
}

// ---------------------------------------------------------------------------
extern "C" void kernel_launch(void* const* d_in, const int* in_sizes, int n_in,
                              void* d_out, int out_size) {
    const float* X[6];
    for (int i = 0; i < 6; i++) X[i] = (const float*)d_in[i];

    const float *W[6], *Bv[6];
    if (n_in >= 8 && in_sizes[7] == DD) {  // interleaved W,b
        for (int i = 0; i < 6; i++) {
            W[i]  = (const float*)d_in[6 + 2 * i];
            Bv[i] = (const float*)d_in[7 + 2 * i];
        }
    } else {  // grouped
        for (int i = 0; i < 6; i++) {
            W[i]  = (const float*)d_in[6 + i];
            Bv[i] = (const float*)d_in[12 + i];
        }
    }

    __half *xh, *wh, *ph, *eBuf;
    float *rsp, *rowsum;
    cudaGetSymbolAddress((void**)&xh, g_xh);
    cudaGetSymbolAddress((void**)&wh, g_wh);
    cudaGetSymbolAddress((void**)&ph, g_ph);
    cudaGetSymbolAddress((void**)&eBuf, g_E);
    cudaGetSymbolAddress((void**)&rsp, g_rsp);
    cudaGetSymbolAddress((void**)&rowsum, g_rowsum);

    __half* XH[6];
    __half* WH[6];
    __half* PH[6];
    for (int i = 0; i < 6; i++) {
        XH[i] = xh + (size_t)i * NC_ * DD;
        WH[i] = wh + (size_t)i * DD * DD;
        PH[i] = ph + (size_t)i * NC_ * DD;
    }
    __half* E1 = eBuf;                       // [NC, NP] exp scores
    __half* E2 = eBuf + (size_t)NC_ * NP_;   // [NP, NC]

    // fp32 -> fp16 conversion of all inputs & weights, one launch
    {
        Src12 s;
        for (int i = 0; i < 6; i++) { s.p[i] = X[i]; s.p[6 + i] = W[i]; }
        conv_h12<<<2400, 256>>>(s, xh, wh);
    }

    cudaFuncSetAttribute(gemm_hb, cudaFuncAttributeMaxDynamicSharedMemorySize, GEMM_SMEM);
    dim3 blk(256);

    // 4 q/k projections -> fp16, one launch (bias per column)
    {
        GemmBatch b;
        b.op[0] = {XH[0], WH[0], Bv[0], PH[0], nullptr, NC_, DD, 1, 1};
        b.op[1] = {XH[1], WH[1], Bv[1], PH[1], nullptr, NC_, DD, 1, 1};
        b.op[2] = {XH[3], WH[3], Bv[3], PH[3], nullptr, NP_, DD, 1, 1};
        b.op[3] = {XH[4], WH[4], Bv[4], PH[4], nullptr, NP_, DD, 1, 1};
        dim3 g(DD / BN, NC_ / BM, 4);
        gemm_hb<<<g, blk, GEMM_SMEM>>>(b, DD);
    }
    // 2 score GEMMs (exp epilogue, fp16 E + rowsum partials)
    // + 2 transposed v projections, ONE merged launch.
    {
        GemmBatch b;
        b.op[0] = {PH[0], PH[4], nullptr, E1, rsp, NC_, NP_, 3, 1};
        b.op[1] = {PH[3], PH[1], nullptr, E2, rsp + (size_t)32 * 4096, NP_, NC_, 3, 1};
        b.op[2] = {WH[2], XH[2], Bv[2], PH[2], nullptr, DD, NC_, 2, 1};
        b.op[3] = {WH[5], XH[5], Bv[5], PH[5], nullptr, DD, NP_, 2, 1};
        dim3 g(NP_ / BN, NC_ / BM, 4);   // v-proj slices exit early
        gemm_hb<<<g, blk, GEMM_SMEM>>>(b, DD);
    }

    rowsum_reduce<<<32, 256>>>(rsp, rowsum);

    float* out = (float*)d_out;
    // 2 PV GEMMs -> fp32 outputs scaled by 1/rowsum, one launch
    {
        GemmBatch b;
        b.op[0] = {E1, PH[5], nullptr, out, rowsum, NC_, DD, 4, 0};
        b.op[1] = {E2, PH[2], nullptr, out + (size_t)NC_ * DD, rowsum + 4096, NP_, DD, 4, 0};
        b.op[2] = b.op[0]; b.op[3] = b.op[0];
        dim3 g(DD / BN, NC_ / BM, 2);
        gemm_hb<<<g, blk, GEMM_SMEM>>>(b, NP_);
    }
}